// round 2
// baseline (speedup 1.0000x reference)
#include <cuda_runtime.h>
#include <cuda_bf16.h>
#include <math.h>

// Problem constants
#define BATCH 4
#define LSEQ  8192
#define EDIM  1024
#define NH    64
#define HD    2
#define FD    128            // NH*HD
#define MTOT  (BATCH*LSEQ)   // 32768
#define TCH   64             // chunk length for scan
#define NC    (LSEQ/TCH)     // 128 chunks per sequence
#define CITOT (BATCH*NC*NH)  // 32768 chunk records

// -------------------- scratch (device globals; no allocation) --------------------
__device__ float g_q[MTOT*FD];
__device__ float g_a[MTOT*FD];
__device__ float g_k[MTOT*FD];
__device__ float g_v[MTOT*FD];
__device__ float g_o[MTOT*FD];

__device__ float g_Ap0[CITOT], g_Ap1[CITOT];
__device__ float g_L00[CITOT], g_L01[CITOT], g_L10[CITOT], g_L11[CITOT];
__device__ float g_I00[CITOT], g_I01[CITOT], g_I10[CITOT], g_I11[CITOT];

// -------------------- packed f32x2 helpers --------------------
__device__ __forceinline__ unsigned long long pack2(float lo, float hi) {
    unsigned long long r;
    asm("mov.b64 %0, {%1,%2};" : "=l"(r) : "f"(lo), "f"(hi));
    return r;
}
__device__ __forceinline__ void fma2(unsigned long long& d, unsigned long long a,
                                     unsigned long long b) {
    asm("fma.rn.f32x2 %0, %1, %2, %0;" : "+l"(d) : "l"(a), "l"(b));
}
__device__ __forceinline__ float2 unpack2(unsigned long long v) {
    float lo, hi;
    asm("mov.b64 {%0,%1}, %2;" : "=f"(lo), "=f"(hi) : "l"(v));
    return make_float2(lo, hi);
}

// -------------------- shared GEMM core: 128x128 tile, BK=16, 256 thr, 8x8/thr ---
__device__ __forceinline__ void gemm_core(const float* __restrict__ Ap, int lda,
                                          const float* __restrict__ Bm, int ldb,
                                          int m0, int n0, int K,
                                          unsigned long long acc[8][4]) {
    __shared__ float As[16][128];
    __shared__ float Bs[16][128];
    int tid = threadIdx.x;
    int tx = tid & 15, ty = tid >> 4;
    int arow = tid >> 2, acol = (tid & 3) * 4;
    int brow = tid >> 5, bcol = (tid & 31) * 4;

    for (int k0 = 0; k0 < K; k0 += 16) {
        #pragma unroll
        for (int s = 0; s < 2; s++) {
            float4 va = *(const float4*)&Ap[(size_t)(m0 + arow + s * 64) * lda + k0 + acol];
            As[acol + 0][arow + s * 64] = va.x;
            As[acol + 1][arow + s * 64] = va.y;
            As[acol + 2][arow + s * 64] = va.z;
            As[acol + 3][arow + s * 64] = va.w;
        }
        #pragma unroll
        for (int s = 0; s < 2; s++) {
            *(float4*)&Bs[brow + s * 8][bcol] =
                *(const float4*)&Bm[(size_t)(k0 + brow + s * 8) * ldb + n0 + bcol];
        }
        __syncthreads();
        #pragma unroll
        for (int kk = 0; kk < 16; kk++) {
            float4 a0 = *(const float4*)&As[kk][ty * 8];
            float4 a1 = *(const float4*)&As[kk][ty * 8 + 4];
            const unsigned long long* bp = (const unsigned long long*)&Bs[kk][tx * 8];
            unsigned long long b0 = bp[0], b1 = bp[1], b2 = bp[2], b3 = bp[3];
            unsigned long long apk[8];
            apk[0] = pack2(a0.x, a0.x); apk[1] = pack2(a0.y, a0.y);
            apk[2] = pack2(a0.z, a0.z); apk[3] = pack2(a0.w, a0.w);
            apk[4] = pack2(a1.x, a1.x); apk[5] = pack2(a1.y, a1.y);
            apk[6] = pack2(a1.z, a1.z); apk[7] = pack2(a1.w, a1.w);
            #pragma unroll
            for (int m = 0; m < 8; m++) {
                fma2(acc[m][0], apk[m], b0);
                fma2(acc[m][1], apk[m], b1);
                fma2(acc[m][2], apk[m], b2);
                fma2(acc[m][3], apk[m], b3);
            }
        }
        __syncthreads();
    }
}

// -------------------- GEMM1: x @ {Wq,Wf,Wi} with fused activations --------------
__global__ void __launch_bounds__(256) gemm1_kernel(const float* __restrict__ x,
                                                    const float* __restrict__ Wq,
                                                    const float* __restrict__ Wf,
                                                    const float* __restrict__ Wi) {
    int mode = blockIdx.y;  // 0=q, 1=f, 2=i
    const float* Bm = (mode == 0) ? Wq : (mode == 1) ? Wf : Wi;
    int m0 = blockIdx.x * 128;
    unsigned long long acc[8][4];
    #pragma unroll
    for (int i = 0; i < 8; i++)
        #pragma unroll
        for (int j = 0; j < 4; j++) acc[i][j] = 0ULL;

    gemm_core(x, EDIM, Bm, FD, m0, 0, EDIM, acc);

    int tx = threadIdx.x & 15, ty = threadIdx.x >> 4;
    const float RS2 = 0.70710678118654752f;  // 1/sqrt(2) (also D^-0.5 scale)
    #pragma unroll
    for (int m = 0; m < 8; m++) {
        size_t r = (size_t)(m0 + ty * 8 + m);
        int c = tx * 8;
        float v[8];
        #pragma unroll
        for (int np = 0; np < 4; np++) {
            float2 p = unpack2(acc[m][np]);
            v[2 * np] = p.x; v[2 * np + 1] = p.y;
        }
        if (mode == 0) {
            #pragma unroll
            for (int j = 0; j < 8; j++) {
                float xv = v[j];
                v[j] = 0.5f * xv * (1.0f + erff(xv * RS2)) * RS2;  // gelu * D^-0.5
            }
            *(float4*)&g_q[r * FD + c]     = make_float4(v[0], v[1], v[2], v[3]);
            *(float4*)&g_q[r * FD + c + 4] = make_float4(v[4], v[5], v[6], v[7]);
        } else if (mode == 1) {
            float av[8], kv[8];
            #pragma unroll
            for (int j = 0; j < 8; j++) {
                float s = 1.0f / (1.0f + expf(-v[j]));
                av[j] = s + 1e-6f;   // decay = exp(log(g+1e-6))
                kv[j] = 1.0f - s;    // k = 1 - g
            }
            *(float4*)&g_a[r * FD + c]     = make_float4(av[0], av[1], av[2], av[3]);
            *(float4*)&g_a[r * FD + c + 4] = make_float4(av[4], av[5], av[6], av[7]);
            *(float4*)&g_k[r * FD + c]     = make_float4(kv[0], kv[1], kv[2], kv[3]);
            *(float4*)&g_k[r * FD + c + 4] = make_float4(kv[4], kv[5], kv[6], kv[7]);
        } else {
            *(float4*)&g_v[r * FD + c]     = make_float4(v[0], v[1], v[2], v[3]);
            *(float4*)&g_v[r * FD + c + 4] = make_float4(v[4], v[5], v[6], v[7]);
        }
    }
}

// -------------------- GEMM2: tanh(o) @ Wo -> output -----------------------------
__global__ void __launch_bounds__(256) gemm2_kernel(const float* __restrict__ Wo,
                                                    float* __restrict__ out) {
    int m0 = blockIdx.x * 128;
    int n0 = blockIdx.y * 128;
    unsigned long long acc[8][4];
    #pragma unroll
    for (int i = 0; i < 8; i++)
        #pragma unroll
        for (int j = 0; j < 4; j++) acc[i][j] = 0ULL;

    gemm_core(g_o, FD, Wo, EDIM, m0, n0, FD, acc);

    int tx = threadIdx.x & 15, ty = threadIdx.x >> 4;
    #pragma unroll
    for (int m = 0; m < 8; m++) {
        size_t r = (size_t)(m0 + ty * 8 + m);
        int c = n0 + tx * 8;
        float v[8];
        #pragma unroll
        for (int np = 0; np < 4; np++) {
            float2 p = unpack2(acc[m][np]);
            v[2 * np] = p.x; v[2 * np + 1] = p.y;
        }
        *(float4*)&out[r * EDIM + c]     = make_float4(v[0], v[1], v[2], v[3]);
        *(float4*)&out[r * EDIM + c + 4] = make_float4(v[4], v[5], v[6], v[7]);
    }
}

// -------------------- Scan pass A: per-chunk local scan -------------------------
// grid = NC blocks, 256 threads; thread = (b = tid>>6, h = tid&63)
__global__ void __launch_bounds__(256) scanA_kernel() {
    int t = blockIdx.x;
    int b = threadIdx.x >> 6;
    int h = threadIdx.x & 63;
    size_t base = ((size_t)b * LSEQ + (size_t)t * TCH) * FD + 2 * h;
    float S00 = 0.f, S01 = 0.f, S10 = 0.f, S11 = 0.f;
    float A0 = 1.f, A1 = 1.f;
    #pragma unroll 4
    for (int i = 0; i < TCH; i++) {
        float2 a  = *(const float2*)&g_a[base];
        float2 kk = *(const float2*)&g_k[base];
        float2 vv = *(const float2*)&g_v[base];
        base += FD;
        S00 = a.x * S00 + kk.x * vv.x;
        S01 = a.x * S01 + kk.x * vv.y;
        S10 = a.y * S10 + kk.y * vv.x;
        S11 = a.y * S11 + kk.y * vv.y;
        A0 *= a.x;
        A1 *= a.y;
    }
    int ci = (b * NC + t) * NH + h;
    g_Ap0[ci] = A0;  g_Ap1[ci] = A1;
    g_L00[ci] = S00; g_L01[ci] = S01;
    g_L10[ci] = S10; g_L11[ci] = S11;
}

// -------------------- Scan pass B: serial combine over chunks -------------------
// grid = 1 block, 256 threads; thread = (b,h)
__global__ void __launch_bounds__(256) scanB_kernel() {
    int b = threadIdx.x >> 6;
    int h = threadIdx.x & 63;
    float S00 = 0.f, S01 = 0.f, S10 = 0.f, S11 = 0.f;
    for (int c = 0; c < NC; c++) {
        int ci = (b * NC + c) * NH + h;
        g_I00[ci] = S00; g_I01[ci] = S01;
        g_I10[ci] = S10; g_I11[ci] = S11;
        float A0 = g_Ap0[ci], A1 = g_Ap1[ci];
        S00 = A0 * S00 + g_L00[ci];
        S01 = A0 * S01 + g_L01[ci];
        S10 = A1 * S10 + g_L10[ci];
        S11 = A1 * S11 + g_L11[ci];
    }
}

// -------------------- Scan pass C: replay with outputs --------------------------
__global__ void __launch_bounds__(256) scanC_kernel() {
    int t = blockIdx.x;
    int b = threadIdx.x >> 6;
    int h = threadIdx.x & 63;
    int ci = (b * NC + t) * NH + h;
    float S00 = g_I00[ci], S01 = g_I01[ci], S10 = g_I10[ci], S11 = g_I11[ci];
    size_t base = ((size_t)b * LSEQ + (size_t)t * TCH) * FD + 2 * h;
    #pragma unroll 4
    for (int i = 0; i < TCH; i++) {
        float2 a  = *(const float2*)&g_a[base];
        float2 kk = *(const float2*)&g_k[base];
        float2 vv = *(const float2*)&g_v[base];
        float2 q  = *(const float2*)&g_q[base];
        S00 = a.x * S00 + kk.x * vv.x;
        S01 = a.x * S01 + kk.x * vv.y;
        S10 = a.y * S10 + kk.y * vv.x;
        S11 = a.y * S11 + kk.y * vv.y;
        float ox = q.x * S00 + q.y * S10;   // o[v] = sum_k q[k]*S[k,v]
        float oy = q.x * S01 + q.y * S11;
        *(float2*)&g_o[base] = make_float2(tanhf(ox), tanhf(oy));
        base += FD;
    }
}

// -------------------- launch --------------------------------------------------
extern "C" void kernel_launch(void* const* d_in, const int* in_sizes, int n_in,
                              void* d_out, int out_size) {
    const float* x  = (const float*)d_in[0];
    const float* Wq = (const float*)d_in[1];
    const float* Wf = (const float*)d_in[2];
    const float* Wi = (const float*)d_in[3];
    const float* Wo = (const float*)d_in[4];
    float* out = (float*)d_out;

    dim3 g1(MTOT / 128, 3);
    gemm1_kernel<<<g1, 256>>>(x, Wq, Wf, Wi);
    scanA_kernel<<<NC, 256>>>();
    scanB_kernel<<<1, 256>>>();
    scanC_kernel<<<NC, 256>>>();
    dim3 g2(MTOT / 128, EDIM / 128);
    gemm2_kernel<<<g2, 256>>>(Wo, out);
}

// round 4
// speedup vs baseline: 1.9295x; 1.9295x over previous
#include <cuda_runtime.h>
#include <cuda_bf16.h>
#include <math.h>
#include <stdint.h>

// ---------------- problem constants ----------------
#define BATCH 4
#define LSEQ  8192
#define EDIM  1024
#define NH    64
#define FD    128
#define MTOT  (BATCH*LSEQ)   // 32768
#define TCH   32             // scan chunk length
#define NC    (LSEQ/TCH)     // 256 chunks per sequence
#define NBH   (BATCH*NH)     // 256 (b,h) pairs

// smem geometry for GEMM staging: rows padded to 72 halves = 144 bytes
#define RSTR  144
#define A_H   0
#define A_L   18432
#define B_H   36864
#define B_L   55296
#define SMEM_BYTES 73728

// ---------------- scratch (device globals) ----------------
__device__ __align__(16) float g_q[MTOT*FD];
__device__ __align__(16) float g_a[MTOT*FD];
__device__ __align__(16) float g_k[MTOT*FD];
__device__ __align__(16) float g_v[MTOT*FD];
__device__ __align__(16) float g_to[MTOT*FD];   // tanh(o)

__device__ __align__(16) float g_Ap0[NBH*NC], g_Ap1[NBH*NC];
__device__ __align__(16) float g_L00[NBH*NC], g_L01[NBH*NC], g_L10[NBH*NC], g_L11[NBH*NC];
__device__ __align__(16) float g_I00[NBH*NC], g_I01[NBH*NC], g_I10[NBH*NC], g_I11[NBH*NC];

// transposed + bf16-split weights: [n][e] with e contiguous (col-major B for mma)
__device__ __align__(16) __nv_bfloat16 g_Wth[3][FD*EDIM];
__device__ __align__(16) __nv_bfloat16 g_Wtl[3][FD*EDIM];
__device__ __align__(16) __nv_bfloat16 g_Woth[EDIM*FD];    // [n=1024][k=128]
__device__ __align__(16) __nv_bfloat16 g_Wotl[EDIM*FD];

// ---------------- helpers ----------------
__device__ __forceinline__ uint32_t smem_u32(const void* p) {
    uint32_t a;
    asm("{ .reg .u64 t; cvta.to.shared.u64 t, %1; cvt.u32.u64 %0, t; }" : "=r"(a) : "l"(p));
    return a;
}
__device__ __forceinline__ uint32_t lds32(uint32_t addr) {
    uint32_t v;
    asm volatile("ld.shared.b32 %0, [%1];" : "=r"(v) : "r"(addr));
    return v;
}
__device__ __forceinline__ void sts64(uint32_t addr, uint32_t a, uint32_t b) {
    asm volatile("st.shared.v2.b32 [%0], {%1,%2};" :: "r"(addr), "r"(a), "r"(b) : "memory");
}
__device__ __forceinline__ void sts128(uint32_t addr, uint32_t a, uint32_t b, uint32_t c, uint32_t d) {
    asm volatile("st.shared.v4.b32 [%0], {%1,%2,%3,%4};" :: "r"(addr), "r"(a), "r"(b), "r"(c), "r"(d) : "memory");
}
__device__ __forceinline__ void mma16816(float* d, uint32_t a0, uint32_t a1, uint32_t a2, uint32_t a3,
                                         uint32_t b0, uint32_t b1) {
    asm volatile(
        "mma.sync.aligned.m16n8k16.row.col.f32.bf16.bf16.f32 "
        "{%0,%1,%2,%3}, {%4,%5,%6,%7}, {%8,%9}, {%0,%1,%2,%3};"
        : "+f"(d[0]), "+f"(d[1]), "+f"(d[2]), "+f"(d[3])
        : "r"(a0), "r"(a1), "r"(a2), "r"(a3), "r"(b0), "r"(b1));
}
__device__ __forceinline__ uint32_t pack_bf16(__nv_bfloat16 a, __nv_bfloat16 b) {
    __nv_bfloat162 t; t.x = a; t.y = b;
    return *reinterpret_cast<uint32_t*>(&t);
}
__device__ __forceinline__ void split2(float f0, float f1, uint32_t& hi, uint32_t& lo) {
    __nv_bfloat16 h0 = __float2bfloat16(f0);
    __nv_bfloat16 h1 = __float2bfloat16(f1);
    hi = pack_bf16(h0, h1);
    lo = pack_bf16(__float2bfloat16(f0 - __bfloat162float(h0)),
                   __float2bfloat16(f1 - __bfloat162float(h1)));
}

// ---------------- weight prep: transpose + bf16 split ----------------
__global__ void __launch_bounds__(256) prep_w_kernel(const float* __restrict__ Wq,
                                                     const float* __restrict__ Wf,
                                                     const float* __restrict__ Wi,
                                                     const float* __restrict__ Wo) {
    int idx = blockIdx.x * 256 + threadIdx.x;
    if (idx < 3 * EDIM * FD) {
        int n = idx & 127, e = (idx >> 7) & 1023, w = idx >> 17;
        const float* W = (w == 0) ? Wq : (w == 1) ? Wf : Wi;
        float v = W[e * FD + n];
        __nv_bfloat16 h = __float2bfloat16(v);
        g_Wth[w][n * EDIM + e] = h;
        g_Wtl[w][n * EDIM + e] = __float2bfloat16(v - __bfloat162float(h));
    } else {
        int j = idx - 3 * EDIM * FD;
        int e = j & 1023, f = j >> 10;
        float v = Wo[f * EDIM + e];
        __nv_bfloat16 h = __float2bfloat16(v);
        g_Woth[e * FD + f] = h;
        g_Wotl[e * FD + f] = __float2bfloat16(v - __bfloat162float(h));
    }
}

// ---------------- GEMM1: x @ {Wq,Wf,Wi}, fused activations ----------------
// grid (3 weights, 256 m-tiles); 256 threads; dyn smem 73728
__global__ void __launch_bounds__(256, 2) gemm1_kernel(const float* __restrict__ x) {
    extern __shared__ char dsm[];
    uint32_t sb = smem_u32(dsm);

    int tid = threadIdx.x, wid = tid >> 5, lid = tid & 31;
    int g = lid >> 2, c = lid & 3;
    int wm = wid & 3, wn = wid >> 2;
    int wsel = blockIdx.x;
    int m0 = blockIdx.y * 128;

    const __nv_bfloat16* __restrict__ Wh = g_Wth[wsel];
    const __nv_bfloat16* __restrict__ Wl = g_Wtl[wsel];

    float acc[2][8][4];
    #pragma unroll
    for (int mt = 0; mt < 2; mt++)
        #pragma unroll
        for (int nt = 0; nt < 8; nt++)
            #pragma unroll
            for (int j = 0; j < 4; j++) acc[mt][nt][j] = 0.f;

    for (int ch = 0; ch < EDIM / 64; ch++) {
        int k0 = ch * 64;
        // fill A: x [128 rows][64 k] fp32 -> bf16 hi/lo
        #pragma unroll
        for (int i = 0; i < 8; i++) {
            int u = tid + 256 * i;          // 2048 float4 groups
            int row = u >> 4, f4 = u & 15;  // 16 float4 per row
            float4 v = *reinterpret_cast<const float4*>(x + (size_t)(m0 + row) * EDIM + k0 + f4 * 4);
            uint32_t h0, l0, h1, l1;
            split2(v.x, v.y, h0, l0); split2(v.z, v.w, h1, l1);
            uint32_t off = row * RSTR + f4 * 8;
            sts64(sb + A_H + off, h0, h1);
            sts64(sb + A_L + off, l0, l1);
        }
        // fill B: Wt [128 n-rows][64 k] pre-split bf16
        #pragma unroll
        for (int i = 0; i < 8; i++) {
            int u = tid + 256 * i;                       // 2048 uint4
            int split = u >> 10, row = (u >> 3) & 127, seg = u & 7;
            uint4 d = *reinterpret_cast<const uint4*>(
                (split ? Wl : Wh) + row * EDIM + k0 + seg * 8);
            sts128(sb + (split ? B_L : B_H) + row * RSTR + seg * 16, d.x, d.y, d.z, d.w);
        }
        __syncthreads();
        #pragma unroll
        for (int kk = 0; kk < 4; kk++) {
            uint32_t acol = (kk * 16 + 2 * c) * 2;
            uint32_t afh[2][4], afl[2][4];
            #pragma unroll
            for (int mt = 0; mt < 2; mt++) {
                uint32_t ab = (wm * 32 + mt * 16 + g) * RSTR + acol;
                afh[mt][0] = lds32(sb + A_H + ab);
                afh[mt][1] = lds32(sb + A_H + ab + 8 * RSTR);
                afh[mt][2] = lds32(sb + A_H + ab + 16);
                afh[mt][3] = lds32(sb + A_H + ab + 8 * RSTR + 16);
                afl[mt][0] = lds32(sb + A_L + ab);
                afl[mt][1] = lds32(sb + A_L + ab + 8 * RSTR);
                afl[mt][2] = lds32(sb + A_L + ab + 16);
                afl[mt][3] = lds32(sb + A_L + ab + 8 * RSTR + 16);
            }
            #pragma unroll
            for (int nt = 0; nt < 8; nt++) {
                uint32_t bb = (wn * 64 + nt * 8 + g) * RSTR + acol;
                uint32_t bh0 = lds32(sb + B_H + bb), bh1 = lds32(sb + B_H + bb + 16);
                uint32_t bl0 = lds32(sb + B_L + bb), bl1 = lds32(sb + B_L + bb + 16);
                #pragma unroll
                for (int mt = 0; mt < 2; mt++) {
                    mma16816(acc[mt][nt], afh[mt][0], afh[mt][1], afh[mt][2], afh[mt][3], bh0, bh1);
                    mma16816(acc[mt][nt], afh[mt][0], afh[mt][1], afh[mt][2], afh[mt][3], bl0, bl1);
                    mma16816(acc[mt][nt], afl[mt][0], afl[mt][1], afl[mt][2], afl[mt][3], bh0, bh1);
                }
            }
        }
        __syncthreads();
    }

    // epilogue: activation + direct stores (D fragment layout)
    const float RS2 = 0.70710678118654752f;
    int row_base = m0 + wm * 32 + g;
    #pragma unroll
    for (int mt = 0; mt < 2; mt++) {
        #pragma unroll
        for (int nt = 0; nt < 8; nt++) {
            int r = row_base + mt * 16;
            int cc = wn * 64 + nt * 8 + 2 * c;
            float* d = acc[mt][nt];
            if (wsel == 0) {
                float q0 = 0.5f * d[0] * (1.0f + erff(d[0] * RS2)) * RS2;
                float q1 = 0.5f * d[1] * (1.0f + erff(d[1] * RS2)) * RS2;
                float q2 = 0.5f * d[2] * (1.0f + erff(d[2] * RS2)) * RS2;
                float q3 = 0.5f * d[3] * (1.0f + erff(d[3] * RS2)) * RS2;
                *(float2*)&g_q[(size_t)r * FD + cc]       = make_float2(q0, q1);
                *(float2*)&g_q[(size_t)(r + 8) * FD + cc] = make_float2(q2, q3);
            } else if (wsel == 1) {
                float s0 = 1.0f / (1.0f + expf(-d[0]));
                float s1 = 1.0f / (1.0f + expf(-d[1]));
                float s2 = 1.0f / (1.0f + expf(-d[2]));
                float s3 = 1.0f / (1.0f + expf(-d[3]));
                *(float2*)&g_a[(size_t)r * FD + cc]       = make_float2(s0 + 1e-6f, s1 + 1e-6f);
                *(float2*)&g_a[(size_t)(r + 8) * FD + cc] = make_float2(s2 + 1e-6f, s3 + 1e-6f);
                *(float2*)&g_k[(size_t)r * FD + cc]       = make_float2(1.0f - s0, 1.0f - s1);
                *(float2*)&g_k[(size_t)(r + 8) * FD + cc] = make_float2(1.0f - s2, 1.0f - s3);
            } else {
                *(float2*)&g_v[(size_t)r * FD + cc]       = make_float2(d[0], d[1]);
                *(float2*)&g_v[(size_t)(r + 8) * FD + cc] = make_float2(d[2], d[3]);
            }
        }
    }
}

// ---------------- GEMM2: tanh_o @ Wo ----------------
// grid (8 n-tiles, 256 m-tiles); 256 threads; dyn smem 73728
__global__ void __launch_bounds__(256, 2) gemm2_kernel(float* __restrict__ out) {
    extern __shared__ char dsm[];
    uint32_t sb = smem_u32(dsm);

    int tid = threadIdx.x, wid = tid >> 5, lid = tid & 31;
    int g = lid >> 2, c = lid & 3;
    int wm = wid & 3, wn = wid >> 2;
    int n0 = blockIdx.x * 128;
    int m0 = blockIdx.y * 128;

    float acc[2][8][4];
    #pragma unroll
    for (int mt = 0; mt < 2; mt++)
        #pragma unroll
        for (int nt = 0; nt < 8; nt++)
            #pragma unroll
            for (int j = 0; j < 4; j++) acc[mt][nt][j] = 0.f;

    for (int ch = 0; ch < 2; ch++) {
        int k0 = ch * 64;
        #pragma unroll
        for (int i = 0; i < 8; i++) {
            int u = tid + 256 * i;
            int row = u >> 4, f4 = u & 15;
            float4 v = *reinterpret_cast<const float4*>(g_to + (size_t)(m0 + row) * FD + k0 + f4 * 4);
            uint32_t h0, l0, h1, l1;
            split2(v.x, v.y, h0, l0); split2(v.z, v.w, h1, l1);
            uint32_t off = row * RSTR + f4 * 8;
            sts64(sb + A_H + off, h0, h1);
            sts64(sb + A_L + off, l0, l1);
        }
        #pragma unroll
        for (int i = 0; i < 8; i++) {
            int u = tid + 256 * i;
            int split = u >> 10, row = (u >> 3) & 127, seg = u & 7;
            uint4 d = *reinterpret_cast<const uint4*>(
                (split ? g_Wotl : g_Woth) + (size_t)(n0 + row) * FD + k0 + seg * 8);
            sts128(sb + (split ? B_L : B_H) + row * RSTR + seg * 16, d.x, d.y, d.z, d.w);
        }
        __syncthreads();
        #pragma unroll
        for (int kk = 0; kk < 4; kk++) {
            uint32_t acol = (kk * 16 + 2 * c) * 2;
            uint32_t afh[2][4], afl[2][4];
            #pragma unroll
            for (int mt = 0; mt < 2; mt++) {
                uint32_t ab = (wm * 32 + mt * 16 + g) * RSTR + acol;
                afh[mt][0] = lds32(sb + A_H + ab);
                afh[mt][1] = lds32(sb + A_H + ab + 8 * RSTR);
                afh[mt][2] = lds32(sb + A_H + ab + 16);
                afh[mt][3] = lds32(sb + A_H + ab + 8 * RSTR + 16);
                afl[mt][0] = lds32(sb + A_L + ab);
                afl[mt][1] = lds32(sb + A_L + ab + 8 * RSTR);
                afl[mt][2] = lds32(sb + A_L + ab + 16);
                afl[mt][3] = lds32(sb + A_L + ab + 8 * RSTR + 16);
            }
            #pragma unroll
            for (int nt = 0; nt < 8; nt++) {
                uint32_t bb = (wn * 64 + nt * 8 + g) * RSTR + acol;
                uint32_t bh0 = lds32(sb + B_H + bb), bh1 = lds32(sb + B_H + bb + 16);
                uint32_t bl0 = lds32(sb + B_L + bb), bl1 = lds32(sb + B_L + bb + 16);
                #pragma unroll
                for (int mt = 0; mt < 2; mt++) {
                    mma16816(acc[mt][nt], afh[mt][0], afh[mt][1], afh[mt][2], afh[mt][3], bh0, bh1);
                    mma16816(acc[mt][nt], afh[mt][0], afh[mt][1], afh[mt][2], afh[mt][3], bl0, bl1);
                    mma16816(acc[mt][nt], afl[mt][0], afl[mt][1], afl[mt][2], afl[mt][3], bh0, bh1);
                }
            }
        }
        __syncthreads();
    }

    int row_base = m0 + wm * 32 + g;
    #pragma unroll
    for (int mt = 0; mt < 2; mt++) {
        #pragma unroll
        for (int nt = 0; nt < 8; nt++) {
            int r = row_base + mt * 16;
            int cc = n0 + wn * 64 + nt * 8 + 2 * c;
            float* d = acc[mt][nt];
            *(float2*)&out[(size_t)r * EDIM + cc]       = make_float2(d[0], d[1]);
            *(float2*)&out[(size_t)(r + 8) * EDIM + cc] = make_float2(d[2], d[3]);
        }
    }
}

// ---------------- scan pass A ----------------
__global__ void __launch_bounds__(256) scanA_kernel() {
    int t = blockIdx.x;
    int b = threadIdx.x >> 6, h = threadIdx.x & 63;
    size_t base = ((size_t)b * LSEQ + (size_t)t * TCH) * FD + 2 * h;
    float S00 = 0.f, S01 = 0.f, S10 = 0.f, S11 = 0.f, A0 = 1.f, A1 = 1.f;
    #pragma unroll 4
    for (int i = 0; i < TCH; i++) {
        float2 a  = *(const float2*)&g_a[base];
        float2 kk = *(const float2*)&g_k[base];
        float2 vv = *(const float2*)&g_v[base];
        base += FD;
        S00 = a.x * S00 + kk.x * vv.x; S01 = a.x * S01 + kk.x * vv.y;
        S10 = a.y * S10 + kk.y * vv.x; S11 = a.y * S11 + kk.y * vv.y;
        A0 *= a.x; A1 *= a.y;
    }
    int ci = (b * NH + h) * NC + t;
    g_Ap0[ci] = A0;  g_Ap1[ci] = A1;
    g_L00[ci] = S00; g_L01[ci] = S01;
    g_L10[ci] = S10; g_L11[ci] = S11;
}

// ---------------- scan pass B ----------------
__global__ void __launch_bounds__(256) scanB_kernel() {
    int bh = threadIdx.x;
    size_t base = (size_t)bh * NC;
    const float4* A0p = (const float4*)(g_Ap0 + base);
    const float4* A1p = (const float4*)(g_Ap1 + base);
    const float4* L00p = (const float4*)(g_L00 + base);
    const float4* L01p = (const float4*)(g_L01 + base);
    const float4* L10p = (const float4*)(g_L10 + base);
    const float4* L11p = (const float4*)(g_L11 + base);
    float4* I00p = (float4*)(g_I00 + base);
    float4* I01p = (float4*)(g_I01 + base);
    float4* I10p = (float4*)(g_I10 + base);
    float4* I11p = (float4*)(g_I11 + base);

    float S00 = 0.f, S01 = 0.f, S10 = 0.f, S11 = 0.f;
    float4 a0 = A0p[0], a1 = A1p[0], l00 = L00p[0], l01 = L01p[0], l10 = L10p[0], l11 = L11p[0];
    #pragma unroll 1
    for (int j = 0; j < NC / 4; j++) {
        float4 na0, na1, nl00, nl01, nl10, nl11;
        if (j + 1 < NC / 4) {
            na0 = A0p[j+1]; na1 = A1p[j+1];
            nl00 = L00p[j+1]; nl01 = L01p[j+1]; nl10 = L10p[j+1]; nl11 = L11p[j+1];
        }
        float4 i00, i01, i10, i11;
        i00.x = S00; i01.x = S01; i10.x = S10; i11.x = S11;
        S00 = a0.x * S00 + l00.x; S01 = a0.x * S01 + l01.x;
        S10 = a1.x * S10 + l10.x; S11 = a1.x * S11 + l11.x;
        i00.y = S00; i01.y = S01; i10.y = S10; i11.y = S11;
        S00 = a0.y * S00 + l00.y; S01 = a0.y * S01 + l01.y;
        S10 = a1.y * S10 + l10.y; S11 = a1.y * S11 + l11.y;
        i00.z = S00; i01.z = S01; i10.z = S10; i11.z = S11;
        S00 = a0.z * S00 + l00.z; S01 = a0.z * S01 + l01.z;
        S10 = a1.z * S10 + l10.z; S11 = a1.z * S11 + l11.z;
        i00.w = S00; i01.w = S01; i10.w = S10; i11.w = S11;
        S00 = a0.w * S00 + l00.w; S01 = a0.w * S01 + l01.w;
        S10 = a1.w * S10 + l10.w; S11 = a1.w * S11 + l11.w;
        I00p[j] = i00; I01p[j] = i01; I10p[j] = i10; I11p[j] = i11;
        a0 = na0; a1 = na1; l00 = nl00; l01 = nl01; l10 = nl10; l11 = nl11;
    }
}

// ---------------- scan pass C: replay + tanh ----------------
__global__ void __launch_bounds__(256) scanC_kernel() {
    int t = blockIdx.x;
    int b = threadIdx.x >> 6, h = threadIdx.x & 63;
    int ci = (b * NH + h) * NC + t;
    float S00 = g_I00[ci], S01 = g_I01[ci], S10 = g_I10[ci], S11 = g_I11[ci];
    size_t base = ((size_t)b * LSEQ + (size_t)t * TCH) * FD + 2 * h;
    #pragma unroll 4
    for (int i = 0; i < TCH; i++) {
        float2 a  = *(const float2*)&g_a[base];
        float2 kk = *(const float2*)&g_k[base];
        float2 vv = *(const float2*)&g_v[base];
        float2 q  = *(const float2*)&g_q[base];
        S00 = a.x * S00 + kk.x * vv.x; S01 = a.x * S01 + kk.x * vv.y;
        S10 = a.y * S10 + kk.y * vv.x; S11 = a.y * S11 + kk.y * vv.y;
        float ox = q.x * S00 + q.y * S10;
        float oy = q.x * S01 + q.y * S11;
        *(float2*)&g_to[base] = make_float2(tanhf(ox), tanhf(oy));
        base += FD;
    }
}

// ---------------- launch ----------------
extern "C" void kernel_launch(void* const* d_in, const int* in_sizes, int n_in,
                              void* d_out, int out_size) {
    const float* x  = (const float*)d_in[0];
    const float* Wq = (const float*)d_in[1];
    const float* Wf = (const float*)d_in[2];
    const float* Wi = (const float*)d_in[3];
    const float* Wo = (const float*)d_in[4];
    float* out = (float*)d_out;

    static int configured = 0;
    if (!configured) {
        cudaFuncSetAttribute(gemm1_kernel, cudaFuncAttributeMaxDynamicSharedMemorySize, SMEM_BYTES);
        cudaFuncSetAttribute(gemm2_kernel, cudaFuncAttributeMaxDynamicSharedMemorySize, SMEM_BYTES);
        configured = 1;
    }

    prep_w_kernel<<<2048, 256>>>(Wq, Wf, Wi, Wo);
    gemm1_kernel<<<dim3(3, MTOT / 128), 256, SMEM_BYTES>>>(x);
    scanA_kernel<<<NC, 256>>>();
    scanB_kernel<<<1, 256>>>();
    scanC_kernel<<<NC, 256>>>();
    gemm2_kernel<<<dim3(8, MTOT / 128), 256, SMEM_BYTES>>>(out);
}

// round 7
// speedup vs baseline: 2.5714x; 1.3327x over previous
#include <cuda_runtime.h>
#include <cuda_bf16.h>
#include <math.h>
#include <stdint.h>

// ---------------- problem constants ----------------
#define BATCH 4
#define LSEQ  8192
#define EDIM  1024
#define NH    64
#define FD    128
#define MTOT  (BATCH*LSEQ)   // 32768
#define TCH   16             // scan chunk length
#define NC    (LSEQ/TCH)     // 512 chunks per sequence
#define NBH   (BATCH*NH)     // 256 (b,h) pairs

// smem geometry for GEMM staging: rows padded to 72 halves = 144 bytes
#define RSTR  144
#define A_H   0
#define A_L   18432
#define B_H   36864
#define B_L   55296
#define SMEM_BYTES 73728

// ---------------- scratch (device globals) ----------------
__device__ __align__(16) float g_q[MTOT*FD];
__device__ __align__(16) float g_a[MTOT*FD];
__device__ __align__(16) float g_k[MTOT*FD];
__device__ __align__(16) float g_v[MTOT*FD];
__device__ __align__(16) float g_to[MTOT*FD];   // tanh(o)

__device__ __align__(16) float g_Ap0[NBH*NC], g_Ap1[NBH*NC];
__device__ __align__(16) float g_L00[NBH*NC], g_L01[NBH*NC], g_L10[NBH*NC], g_L11[NBH*NC];
__device__ __align__(16) float g_I00[NBH*NC], g_I01[NBH*NC], g_I10[NBH*NC], g_I11[NBH*NC];

// transposed + bf16-split weights: [n][e] with e contiguous (col-major B for mma)
__device__ __align__(16) __nv_bfloat16 g_Wth[3][FD*EDIM];
__device__ __align__(16) __nv_bfloat16 g_Wtl[3][FD*EDIM];
__device__ __align__(16) __nv_bfloat16 g_Woth[EDIM*FD];    // [n=1024][k=128]
__device__ __align__(16) __nv_bfloat16 g_Wotl[EDIM*FD];

// ---------------- helpers ----------------
__device__ __forceinline__ uint32_t smem_u32(const void* p) {
    uint32_t a;
    asm("{ .reg .u64 t; cvta.to.shared.u64 t, %1; cvt.u32.u64 %0, t; }" : "=r"(a) : "l"(p));
    return a;
}
__device__ __forceinline__ uint32_t lds32(uint32_t addr) {
    uint32_t v;
    asm volatile("ld.shared.b32 %0, [%1];" : "=r"(v) : "r"(addr));
    return v;
}
__device__ __forceinline__ void sts64(uint32_t addr, uint32_t a, uint32_t b) {
    asm volatile("st.shared.v2.b32 [%0], {%1,%2};" :: "r"(addr), "r"(a), "r"(b) : "memory");
}
__device__ __forceinline__ void sts128(uint32_t addr, uint32_t a, uint32_t b, uint32_t c, uint32_t d) {
    asm volatile("st.shared.v4.b32 [%0], {%1,%2,%3,%4};" :: "r"(addr), "r"(a), "r"(b), "r"(c), "r"(d) : "memory");
}
__device__ __forceinline__ void mma16816(float* d, uint32_t a0, uint32_t a1, uint32_t a2, uint32_t a3,
                                         uint32_t b0, uint32_t b1) {
    asm volatile(
        "mma.sync.aligned.m16n8k16.row.col.f32.bf16.bf16.f32 "
        "{%0,%1,%2,%3}, {%4,%5,%6,%7}, {%8,%9}, {%0,%1,%2,%3};"
        : "+f"(d[0]), "+f"(d[1]), "+f"(d[2]), "+f"(d[3])
        : "r"(a0), "r"(a1), "r"(a2), "r"(a3), "r"(b0), "r"(b1));
}
__device__ __forceinline__ uint32_t pack_bf16(__nv_bfloat16 a, __nv_bfloat16 b) {
    __nv_bfloat162 t; t.x = a; t.y = b;
    return *reinterpret_cast<uint32_t*>(&t);
}
__device__ __forceinline__ void split2(float f0, float f1, uint32_t& hi, uint32_t& lo) {
    __nv_bfloat16 h0 = __float2bfloat16(f0);
    __nv_bfloat16 h1 = __float2bfloat16(f1);
    hi = pack_bf16(h0, h1);
    lo = pack_bf16(__float2bfloat16(f0 - __bfloat162float(h0)),
                   __float2bfloat16(f1 - __bfloat162float(h1)));
}

// ---------------- weight prep: transpose + bf16 split ----------------
__global__ void __launch_bounds__(256) prep_w_kernel(const float* __restrict__ Wq,
                                                     const float* __restrict__ Wf,
                                                     const float* __restrict__ Wi,
                                                     const float* __restrict__ Wo) {
    int idx = blockIdx.x * 256 + threadIdx.x;
    if (idx < 3 * EDIM * FD) {
        int n = idx & 127, e = (idx >> 7) & 1023, w = idx >> 17;
        const float* W = (w == 0) ? Wq : (w == 1) ? Wf : Wi;
        float v = W[e * FD + n];
        __nv_bfloat16 h = __float2bfloat16(v);
        g_Wth[w][n * EDIM + e] = h;
        g_Wtl[w][n * EDIM + e] = __float2bfloat16(v - __bfloat162float(h));
    } else {
        int j = idx - 3 * EDIM * FD;
        int e = j & 1023, f = j >> 10;
        float v = Wo[f * EDIM + e];
        __nv_bfloat16 h = __float2bfloat16(v);
        g_Woth[e * FD + f] = h;
        g_Wotl[e * FD + f] = __float2bfloat16(v - __bfloat162float(h));
    }
}

// ---------------- GEMM1: x @ {Wq,Wf,Wi}, fused activations ----------------
// grid (3 weights, 256 m-tiles); 256 threads; dyn smem 73728
__global__ void __launch_bounds__(256, 2) gemm1_kernel(const float* __restrict__ x) {
    extern __shared__ char dsm[];
    uint32_t sb = smem_u32(dsm);

    int tid = threadIdx.x, wid = tid >> 5, lid = tid & 31;
    int g = lid >> 2, c = lid & 3;
    int wm = wid & 3, wn = wid >> 2;
    int wsel = blockIdx.x;
    int m0 = blockIdx.y * 128;

    const __nv_bfloat16* __restrict__ Wh = g_Wth[wsel];
    const __nv_bfloat16* __restrict__ Wl = g_Wtl[wsel];

    float acc[2][8][4];
    #pragma unroll
    for (int mt = 0; mt < 2; mt++)
        #pragma unroll
        for (int nt = 0; nt < 8; nt++)
            #pragma unroll
            for (int j = 0; j < 4; j++) acc[mt][nt][j] = 0.f;

    for (int ch = 0; ch < EDIM / 64; ch++) {
        int k0 = ch * 64;
        // fill A: x [128 rows][64 k] fp32 -> bf16 hi/lo
        #pragma unroll
        for (int i = 0; i < 8; i++) {
            int u = tid + 256 * i;          // 2048 float4 groups
            int row = u >> 4, f4 = u & 15;  // 16 float4 per row
            float4 v = *reinterpret_cast<const float4*>(x + (size_t)(m0 + row) * EDIM + k0 + f4 * 4);
            uint32_t h0, l0, h1, l1;
            split2(v.x, v.y, h0, l0); split2(v.z, v.w, h1, l1);
            uint32_t off = row * RSTR + f4 * 8;
            sts64(sb + A_H + off, h0, h1);
            sts64(sb + A_L + off, l0, l1);
        }
        // fill B: Wt [128 n-rows][64 k] pre-split bf16
        #pragma unroll
        for (int i = 0; i < 8; i++) {
            int u = tid + 256 * i;                       // 2048 uint4
            int split = u >> 10, row = (u >> 3) & 127, seg = u & 7;
            uint4 d = *reinterpret_cast<const uint4*>(
                (split ? Wl : Wh) + row * EDIM + k0 + seg * 8);
            sts128(sb + (split ? B_L : B_H) + row * RSTR + seg * 16, d.x, d.y, d.z, d.w);
        }
        __syncthreads();
        #pragma unroll
        for (int kk = 0; kk < 4; kk++) {
            uint32_t acol = (kk * 16 + 2 * c) * 2;
            uint32_t afh[2][4], afl[2][4];
            #pragma unroll
            for (int mt = 0; mt < 2; mt++) {
                uint32_t ab = (wm * 32 + mt * 16 + g) * RSTR + acol;
                afh[mt][0] = lds32(sb + A_H + ab);
                afh[mt][1] = lds32(sb + A_H + ab + 8 * RSTR);
                afh[mt][2] = lds32(sb + A_H + ab + 16);
                afh[mt][3] = lds32(sb + A_H + ab + 8 * RSTR + 16);
                afl[mt][0] = lds32(sb + A_L + ab);
                afl[mt][1] = lds32(sb + A_L + ab + 8 * RSTR);
                afl[mt][2] = lds32(sb + A_L + ab + 16);
                afl[mt][3] = lds32(sb + A_L + ab + 8 * RSTR + 16);
            }
            #pragma unroll
            for (int nt = 0; nt < 8; nt++) {
                uint32_t bb = (wn * 64 + nt * 8 + g) * RSTR + acol;
                uint32_t bh0 = lds32(sb + B_H + bb), bh1 = lds32(sb + B_H + bb + 16);
                uint32_t bl0 = lds32(sb + B_L + bb), bl1 = lds32(sb + B_L + bb + 16);
                #pragma unroll
                for (int mt = 0; mt < 2; mt++) {
                    mma16816(acc[mt][nt], afh[mt][0], afh[mt][1], afh[mt][2], afh[mt][3], bh0, bh1);
                    mma16816(acc[mt][nt], afh[mt][0], afh[mt][1], afh[mt][2], afh[mt][3], bl0, bl1);
                    mma16816(acc[mt][nt], afl[mt][0], afl[mt][1], afl[mt][2], afl[mt][3], bh0, bh1);
                }
            }
        }
        __syncthreads();
    }

    // epilogue: activation + direct stores (D fragment layout)
    const float RS2 = 0.70710678118654752f;
    int row_base = m0 + wm * 32 + g;
    #pragma unroll
    for (int mt = 0; mt < 2; mt++) {
        #pragma unroll
        for (int nt = 0; nt < 8; nt++) {
            int r = row_base + mt * 16;
            int cc = wn * 64 + nt * 8 + 2 * c;
            float* d = acc[mt][nt];
            if (wsel == 0) {
                float q0 = 0.5f * d[0] * (1.0f + erff(d[0] * RS2)) * RS2;
                float q1 = 0.5f * d[1] * (1.0f + erff(d[1] * RS2)) * RS2;
                float q2 = 0.5f * d[2] * (1.0f + erff(d[2] * RS2)) * RS2;
                float q3 = 0.5f * d[3] * (1.0f + erff(d[3] * RS2)) * RS2;
                *(float2*)&g_q[(size_t)r * FD + cc]       = make_float2(q0, q1);
                *(float2*)&g_q[(size_t)(r + 8) * FD + cc] = make_float2(q2, q3);
            } else if (wsel == 1) {
                float s0 = 1.0f / (1.0f + expf(-d[0]));
                float s1 = 1.0f / (1.0f + expf(-d[1]));
                float s2 = 1.0f / (1.0f + expf(-d[2]));
                float s3 = 1.0f / (1.0f + expf(-d[3]));
                *(float2*)&g_a[(size_t)r * FD + cc]       = make_float2(s0 + 1e-6f, s1 + 1e-6f);
                *(float2*)&g_a[(size_t)(r + 8) * FD + cc] = make_float2(s2 + 1e-6f, s3 + 1e-6f);
                *(float2*)&g_k[(size_t)r * FD + cc]       = make_float2(1.0f - s0, 1.0f - s1);
                *(float2*)&g_k[(size_t)(r + 8) * FD + cc] = make_float2(1.0f - s2, 1.0f - s3);
            } else {
                *(float2*)&g_v[(size_t)r * FD + cc]       = make_float2(d[0], d[1]);
                *(float2*)&g_v[(size_t)(r + 8) * FD + cc] = make_float2(d[2], d[3]);
            }
        }
    }
}

// ---------------- GEMM2: tanh_o @ Wo ----------------
// grid (8 n-tiles, 256 m-tiles); 256 threads; dyn smem 73728
__global__ void __launch_bounds__(256, 2) gemm2_kernel(float* __restrict__ out) {
    extern __shared__ char dsm[];
    uint32_t sb = smem_u32(dsm);

    int tid = threadIdx.x, wid = tid >> 5, lid = tid & 31;
    int g = lid >> 2, c = lid & 3;
    int wm = wid & 3, wn = wid >> 2;
    int n0 = blockIdx.x * 128;
    int m0 = blockIdx.y * 128;

    float acc[2][8][4];
    #pragma unroll
    for (int mt = 0; mt < 2; mt++)
        #pragma unroll
        for (int nt = 0; nt < 8; nt++)
            #pragma unroll
            for (int j = 0; j < 4; j++) acc[mt][nt][j] = 0.f;

    for (int ch = 0; ch < 2; ch++) {
        int k0 = ch * 64;
        #pragma unroll
        for (int i = 0; i < 8; i++) {
            int u = tid + 256 * i;
            int row = u >> 4, f4 = u & 15;
            float4 v = *reinterpret_cast<const float4*>(g_to + (size_t)(m0 + row) * FD + k0 + f4 * 4);
            uint32_t h0, l0, h1, l1;
            split2(v.x, v.y, h0, l0); split2(v.z, v.w, h1, l1);
            uint32_t off = row * RSTR + f4 * 8;
            sts64(sb + A_H + off, h0, h1);
            sts64(sb + A_L + off, l0, l1);
        }
        #pragma unroll
        for (int i = 0; i < 8; i++) {
            int u = tid + 256 * i;
            int split = u >> 10, row = (u >> 3) & 127, seg = u & 7;
            uint4 d = *reinterpret_cast<const uint4*>(
                (split ? g_Wotl : g_Woth) + (size_t)(n0 + row) * FD + k0 + seg * 8);
            sts128(sb + (split ? B_L : B_H) + row * RSTR + seg * 16, d.x, d.y, d.z, d.w);
        }
        __syncthreads();
        #pragma unroll
        for (int kk = 0; kk < 4; kk++) {
            uint32_t acol = (kk * 16 + 2 * c) * 2;
            uint32_t afh[2][4], afl[2][4];
            #pragma unroll
            for (int mt = 0; mt < 2; mt++) {
                uint32_t ab = (wm * 32 + mt * 16 + g) * RSTR + acol;
                afh[mt][0] = lds32(sb + A_H + ab);
                afh[mt][1] = lds32(sb + A_H + ab + 8 * RSTR);
                afh[mt][2] = lds32(sb + A_H + ab + 16);
                afh[mt][3] = lds32(sb + A_H + ab + 8 * RSTR + 16);
                afl[mt][0] = lds32(sb + A_L + ab);
                afl[mt][1] = lds32(sb + A_L + ab + 8 * RSTR);
                afl[mt][2] = lds32(sb + A_L + ab + 16);
                afl[mt][3] = lds32(sb + A_L + ab + 8 * RSTR + 16);
            }
            #pragma unroll
            for (int nt = 0; nt < 8; nt++) {
                uint32_t bb = (wn * 64 + nt * 8 + g) * RSTR + acol;
                uint32_t bh0 = lds32(sb + B_H + bb), bh1 = lds32(sb + B_H + bb + 16);
                uint32_t bl0 = lds32(sb + B_L + bb), bl1 = lds32(sb + B_L + bb + 16);
                #pragma unroll
                for (int mt = 0; mt < 2; mt++) {
                    mma16816(acc[mt][nt], afh[mt][0], afh[mt][1], afh[mt][2], afh[mt][3], bh0, bh1);
                    mma16816(acc[mt][nt], afh[mt][0], afh[mt][1], afh[mt][2], afh[mt][3], bl0, bl1);
                    mma16816(acc[mt][nt], afl[mt][0], afl[mt][1], afl[mt][2], afl[mt][3], bh0, bh1);
                }
            }
        }
        __syncthreads();
    }

    int row_base = m0 + wm * 32 + g;
    #pragma unroll
    for (int mt = 0; mt < 2; mt++) {
        #pragma unroll
        for (int nt = 0; nt < 8; nt++) {
            int r = row_base + mt * 16;
            int cc = n0 + wn * 64 + nt * 8 + 2 * c;
            float* d = acc[mt][nt];
            *(float2*)&out[(size_t)r * EDIM + cc]       = make_float2(d[0], d[1]);
            *(float2*)&out[(size_t)(r + 8) * EDIM + cc] = make_float2(d[2], d[3]);
        }
    }
}

// ---------------- scan pass A: per-chunk local scan ----------------
// grid = NC blocks, 256 threads; thread = (b = tid>>6, h = tid&63)
__global__ void __launch_bounds__(256) scanA_kernel() {
    int t = blockIdx.x;
    int b = threadIdx.x >> 6, h = threadIdx.x & 63;
    size_t base = ((size_t)b * LSEQ + (size_t)t * TCH) * FD + 2 * h;
    float S00 = 0.f, S01 = 0.f, S10 = 0.f, S11 = 0.f, A0 = 1.f, A1 = 1.f;
    #pragma unroll 4
    for (int i = 0; i < TCH; i++) {
        float2 a  = *(const float2*)&g_a[base];
        float2 kk = *(const float2*)&g_k[base];
        float2 vv = *(const float2*)&g_v[base];
        base += FD;
        S00 = a.x * S00 + kk.x * vv.x; S01 = a.x * S01 + kk.x * vv.y;
        S10 = a.y * S10 + kk.y * vv.x; S11 = a.y * S11 + kk.y * vv.y;
        A0 *= a.x; A1 *= a.y;
    }
    int ci = (b * NH + h) * NC + t;
    g_Ap0[ci] = A0;  g_Ap1[ci] = A1;
    g_L00[ci] = S00; g_L01[ci] = S01;
    g_L10[ci] = S10; g_L11[ci] = S11;
}

// ---------------- scan pass B: parallel Kogge-Stone combine over chunks --------
// grid = NBH blocks (one per b,h), NC threads; composition op:
//   later∘earlier : A = A_t*A_p ; L = A_t*L_p + L_t  (per k-component)
__global__ void __launch_bounds__(NC) scanB_kernel() {
    __shared__ float sA0[NC], sA1[NC];
    __shared__ float s00[NC], s01[NC], s10[NC], s11[NC];
    int bh = blockIdx.x;
    int t = threadIdx.x;
    size_t base = (size_t)bh * NC + t;

    float a0 = g_Ap0[base], a1 = g_Ap1[base];
    float l00 = g_L00[base], l01 = g_L01[base];
    float l10 = g_L10[base], l11 = g_L11[base];
    sA0[t] = a0; sA1[t] = a1;
    s00[t] = l00; s01[t] = l01; s10[t] = l10; s11[t] = l11;
    __syncthreads();

    #pragma unroll
    for (int d = 1; d < NC; d <<= 1) {
        float pa0 = 0.f, pa1 = 0.f, p00 = 0.f, p01 = 0.f, p10 = 0.f, p11 = 0.f;
        if (t >= d) {
            pa0 = sA0[t - d]; pa1 = sA1[t - d];
            p00 = s00[t - d]; p01 = s01[t - d];
            p10 = s10[t - d]; p11 = s11[t - d];
        }
        __syncthreads();
        if (t >= d) {
            l00 = fmaf(a0, p00, l00); l01 = fmaf(a0, p01, l01);
            l10 = fmaf(a1, p10, l10); l11 = fmaf(a1, p11, l11);
            a0 *= pa0; a1 *= pa1;
            sA0[t] = a0; sA1[t] = a1;
            s00[t] = l00; s01[t] = l01; s10[t] = l10; s11[t] = l11;
        }
        __syncthreads();
    }

    // exclusive result: incoming state at chunk t = inclusive L of chunk t-1
    float i00 = 0.f, i01 = 0.f, i10 = 0.f, i11 = 0.f;
    if (t > 0) {
        i00 = s00[t - 1]; i01 = s01[t - 1];
        i10 = s10[t - 1]; i11 = s11[t - 1];
    }
    g_I00[base] = i00; g_I01[base] = i01;
    g_I10[base] = i10; g_I11[base] = i11;
}

// ---------------- scan pass C: replay + tanh ----------------
__global__ void __launch_bounds__(256) scanC_kernel() {
    int t = blockIdx.x;
    int b = threadIdx.x >> 6, h = threadIdx.x & 63;
    int ci = (b * NH + h) * NC + t;
    float S00 = g_I00[ci], S01 = g_I01[ci], S10 = g_I10[ci], S11 = g_I11[ci];
    size_t base = ((size_t)b * LSEQ + (size_t)t * TCH) * FD + 2 * h;
    #pragma unroll 4
    for (int i = 0; i < TCH; i++) {
        float2 a  = *(const float2*)&g_a[base];
        float2 kk = *(const float2*)&g_k[base];
        float2 vv = *(const float2*)&g_v[base];
        float2 q  = *(const float2*)&g_q[base];
        S00 = a.x * S00 + kk.x * vv.x; S01 = a.x * S01 + kk.x * vv.y;
        S10 = a.y * S10 + kk.y * vv.x; S11 = a.y * S11 + kk.y * vv.y;
        float ox = q.x * S00 + q.y * S10;
        float oy = q.x * S01 + q.y * S11;
        *(float2*)&g_to[base] = make_float2(tanhf(ox), tanhf(oy));
        base += FD;
    }
}

// ---------------- launch ----------------
extern "C" void kernel_launch(void* const* d_in, const int* in_sizes, int n_in,
                              void* d_out, int out_size) {
    const float* x  = (const float*)d_in[0];
    const float* Wq = (const float*)d_in[1];
    const float* Wf = (const float*)d_in[2];
    const float* Wi = (const float*)d_in[3];
    const float* Wo = (const float*)d_in[4];
    float* out = (float*)d_out;

    static int configured = 0;
    if (!configured) {
        cudaFuncSetAttribute(gemm1_kernel, cudaFuncAttributeMaxDynamicSharedMemorySize, SMEM_BYTES);
        cudaFuncSetAttribute(gemm2_kernel, cudaFuncAttributeMaxDynamicSharedMemorySize, SMEM_BYTES);
        configured = 1;
    }

    prep_w_kernel<<<2048, 256>>>(Wq, Wf, Wi, Wo);
    gemm1_kernel<<<dim3(3, MTOT / 128), 256, SMEM_BYTES>>>(x);
    scanA_kernel<<<NC, 256>>>();
    scanB_kernel<<<NBH, NC>>>();
    scanC_kernel<<<NC, 256>>>();
    gemm2_kernel<<<dim3(8, MTOT / 128), 256, SMEM_BYTES>>>(out);
}

// round 8
// speedup vs baseline: 2.6721x; 1.0392x over previous
#include <cuda_runtime.h>
#include <cuda_bf16.h>
#include <math.h>
#include <stdint.h>

// ---------------- problem constants ----------------
#define BATCH 4
#define LSEQ  8192
#define EDIM  1024
#define NH    64
#define FD    128
#define MTOT  (BATCH*LSEQ)   // 32768
#define TCH   16             // scan chunk length
#define NC    (LSEQ/TCH)     // 512 chunks per sequence
#define NBH   (BATCH*NH)     // 256 (b,h) pairs

// smem geometry for GEMM staging: rows padded to 72 halves = 144 bytes
#define RSTR  144
#define A_H   0
#define A_L   18432
#define B_H   36864
#define B_L   55296
#define SMEM_BYTES 73728

// ---------------- scratch (device globals) ----------------
__device__ __align__(16) float g_q[MTOT*FD];
__device__ __align__(16) float g_a[MTOT*FD];
__device__ __align__(16) float g_k[MTOT*FD];
__device__ __align__(16) float g_v[MTOT*FD];
__device__ __align__(16) float g_to[MTOT*FD];   // tanh(o)

__device__ __align__(16) float g_Ap0[NBH*NC], g_Ap1[NBH*NC];
__device__ __align__(16) float g_L00[NBH*NC], g_L01[NBH*NC], g_L10[NBH*NC], g_L11[NBH*NC];
__device__ __align__(16) float g_I00[NBH*NC], g_I01[NBH*NC], g_I10[NBH*NC], g_I11[NBH*NC];

// transposed + bf16-split weights: [n][e] with e contiguous (col-major B for mma)
__device__ __align__(16) __nv_bfloat16 g_Wth[3][FD*EDIM];
__device__ __align__(16) __nv_bfloat16 g_Wtl[3][FD*EDIM];
__device__ __align__(16) __nv_bfloat16 g_Woth[EDIM*FD];    // [n=1024][k=128]
__device__ __align__(16) __nv_bfloat16 g_Wotl[EDIM*FD];

// ---------------- helpers ----------------
__device__ __forceinline__ uint32_t smem_u32(const void* p) {
    uint32_t a;
    asm("{ .reg .u64 t; cvta.to.shared.u64 t, %1; cvt.u32.u64 %0, t; }" : "=r"(a) : "l"(p));
    return a;
}
__device__ __forceinline__ void sts64(uint32_t addr, uint32_t a, uint32_t b) {
    asm volatile("st.shared.v2.b32 [%0], {%1,%2};" :: "r"(addr), "r"(a), "r"(b) : "memory");
}
__device__ __forceinline__ void sts128(uint32_t addr, uint32_t a, uint32_t b, uint32_t c, uint32_t d) {
    asm volatile("st.shared.v4.b32 [%0], {%1,%2,%3,%4};" :: "r"(addr), "r"(a), "r"(b), "r"(c), "r"(d) : "memory");
}
__device__ __forceinline__ void ldsm4(uint32_t* r, uint32_t addr) {
    asm volatile("ldmatrix.sync.aligned.m8n8.x4.shared.b16 {%0,%1,%2,%3}, [%4];"
        : "=r"(r[0]), "=r"(r[1]), "=r"(r[2]), "=r"(r[3]) : "r"(addr));
}
__device__ __forceinline__ void mma16816(float* d, const uint32_t* a, uint32_t b0, uint32_t b1) {
    asm volatile(
        "mma.sync.aligned.m16n8k16.row.col.f32.bf16.bf16.f32 "
        "{%0,%1,%2,%3}, {%4,%5,%6,%7}, {%8,%9}, {%0,%1,%2,%3};"
        : "+f"(d[0]), "+f"(d[1]), "+f"(d[2]), "+f"(d[3])
        : "r"(a[0]), "r"(a[1]), "r"(a[2]), "r"(a[3]), "r"(b0), "r"(b1));
}
__device__ __forceinline__ uint32_t pack_bf16(__nv_bfloat16 a, __nv_bfloat16 b) {
    __nv_bfloat162 t; t.x = a; t.y = b;
    return *reinterpret_cast<uint32_t*>(&t);
}
__device__ __forceinline__ void split2(float f0, float f1, uint32_t& hi, uint32_t& lo) {
    __nv_bfloat16 h0 = __float2bfloat16(f0);
    __nv_bfloat16 h1 = __float2bfloat16(f1);
    hi = pack_bf16(h0, h1);
    lo = pack_bf16(__float2bfloat16(f0 - __bfloat162float(h0)),
                   __float2bfloat16(f1 - __bfloat162float(h1)));
}

// fragment-load lane offsets (bytes), shared by both GEMMs
__device__ __forceinline__ uint32_t a_lane_off(int wm, int lid) {
    return (uint32_t)((wm * 32 + (lid & 15)) * RSTR + ((lid >> 4) & 1) * 16);
}
__device__ __forceinline__ uint32_t b_lane_off(int wn, int lid) {
    return (uint32_t)((wn * 64 + ((lid & 16) >> 1) + (lid & 7)) * RSTR + ((lid & 8) << 1));
}

// mainloop step: one k64 chunk's 4 k16 sub-steps on staged smem
__device__ __forceinline__ void gemm_compute64(uint32_t sb, uint32_t aoff, uint32_t boff,
                                               float acc[2][8][4]) {
    #pragma unroll
    for (int kk = 0; kk < 4; kk++) {
        uint32_t kof = kk * 32;
        uint32_t ah0[4], ah1[4], al0[4], al1[4];
        ldsm4(ah0, sb + A_H + aoff + kof);
        ldsm4(ah1, sb + A_H + aoff + 16 * RSTR + kof);
        ldsm4(al0, sb + A_L + aoff + kof);
        ldsm4(al1, sb + A_L + aoff + 16 * RSTR + kof);
        #pragma unroll
        for (int p = 0; p < 4; p++) {
            uint32_t bh[4], bl[4];
            ldsm4(bh, sb + B_H + boff + p * 16 * RSTR + kof);
            ldsm4(bl, sb + B_L + boff + p * 16 * RSTR + kof);
            // nt = 2p uses bh[0],bh[1]/bl[0],bl[1]; nt = 2p+1 uses [2],[3]
            mma16816(acc[0][2*p],   ah0, bh[0], bh[1]);
            mma16816(acc[0][2*p],   ah0, bl[0], bl[1]);
            mma16816(acc[0][2*p],   al0, bh[0], bh[1]);
            mma16816(acc[1][2*p],   ah1, bh[0], bh[1]);
            mma16816(acc[1][2*p],   ah1, bl[0], bl[1]);
            mma16816(acc[1][2*p],   al1, bh[0], bh[1]);
            mma16816(acc[0][2*p+1], ah0, bh[2], bh[3]);
            mma16816(acc[0][2*p+1], ah0, bl[2], bl[3]);
            mma16816(acc[0][2*p+1], al0, bh[2], bh[3]);
            mma16816(acc[1][2*p+1], ah1, bh[2], bh[3]);
            mma16816(acc[1][2*p+1], ah1, bl[2], bl[3]);
            mma16816(acc[1][2*p+1], al1, bh[2], bh[3]);
        }
    }
}

// ---------------- weight prep: transpose + bf16 split ----------------
__global__ void __launch_bounds__(256) prep_w_kernel(const float* __restrict__ Wq,
                                                     const float* __restrict__ Wf,
                                                     const float* __restrict__ Wi,
                                                     const float* __restrict__ Wo) {
    int idx = blockIdx.x * 256 + threadIdx.x;
    if (idx < 3 * EDIM * FD) {
        int n = idx & 127, e = (idx >> 7) & 1023, w = idx >> 17;
        const float* W = (w == 0) ? Wq : (w == 1) ? Wf : Wi;
        float v = W[e * FD + n];
        __nv_bfloat16 h = __float2bfloat16(v);
        g_Wth[w][n * EDIM + e] = h;
        g_Wtl[w][n * EDIM + e] = __float2bfloat16(v - __bfloat162float(h));
    } else {
        int j = idx - 3 * EDIM * FD;
        int e = j & 1023, f = j >> 10;
        float v = Wo[f * EDIM + e];
        __nv_bfloat16 h = __float2bfloat16(v);
        g_Woth[e * FD + f] = h;
        g_Wotl[e * FD + f] = __float2bfloat16(v - __bfloat162float(h));
    }
}

// ---------------- GEMM1: x @ {Wq,Wf,Wi}, fused activations ----------------
// grid (3 weights, 256 m-tiles); 256 threads; dyn smem 73728
__global__ void __launch_bounds__(256, 2) gemm1_kernel(const float* __restrict__ x) {
    extern __shared__ char dsm[];
    uint32_t sb = smem_u32(dsm);

    int tid = threadIdx.x, wid = tid >> 5, lid = tid & 31;
    int g = lid >> 2, c = lid & 3;
    int wm = wid & 3, wn = wid >> 2;
    int wsel = blockIdx.x;
    int m0 = blockIdx.y * 128;

    const __nv_bfloat16* __restrict__ Wh = g_Wth[wsel];
    const __nv_bfloat16* __restrict__ Wl = g_Wtl[wsel];

    uint32_t aoff = a_lane_off(wm, lid);
    uint32_t boff = b_lane_off(wn, lid);

    float acc[2][8][4];
    #pragma unroll
    for (int mt = 0; mt < 2; mt++)
        #pragma unroll
        for (int nt = 0; nt < 8; nt++)
            #pragma unroll
            for (int j = 0; j < 4; j++) acc[mt][nt][j] = 0.f;

    for (int ch = 0; ch < EDIM / 64; ch++) {
        int k0 = ch * 64;
        // fill A: x [128 rows][64 k] fp32 -> bf16 hi/lo
        #pragma unroll
        for (int i = 0; i < 8; i++) {
            int u = tid + 256 * i;          // 2048 float4 groups
            int row = u >> 4, f4 = u & 15;  // 16 float4 per row
            float4 v = *reinterpret_cast<const float4*>(x + (size_t)(m0 + row) * EDIM + k0 + f4 * 4);
            uint32_t h0, l0, h1, l1;
            split2(v.x, v.y, h0, l0); split2(v.z, v.w, h1, l1);
            uint32_t off = row * RSTR + f4 * 8;
            sts64(sb + A_H + off, h0, h1);
            sts64(sb + A_L + off, l0, l1);
        }
        // fill B: Wt [128 n-rows][64 k] pre-split bf16
        #pragma unroll
        for (int i = 0; i < 8; i++) {
            int u = tid + 256 * i;                       // 2048 uint4
            int split = u >> 10, row = (u >> 3) & 127, seg = u & 7;
            uint4 d = *reinterpret_cast<const uint4*>(
                (split ? Wl : Wh) + row * EDIM + k0 + seg * 8);
            sts128(sb + (split ? B_L : B_H) + row * RSTR + seg * 16, d.x, d.y, d.z, d.w);
        }
        __syncthreads();
        gemm_compute64(sb, aoff, boff, acc);
        __syncthreads();
    }

    // epilogue: activation + direct stores (D fragment layout)
    const float RS2 = 0.70710678118654752f;
    int row_base = m0 + wm * 32 + g;
    #pragma unroll
    for (int mt = 0; mt < 2; mt++) {
        #pragma unroll
        for (int nt = 0; nt < 8; nt++) {
            int r = row_base + mt * 16;
            int cc = wn * 64 + nt * 8 + 2 * c;
            float* d = acc[mt][nt];
            if (wsel == 0) {
                float q0 = 0.5f * d[0] * (1.0f + erff(d[0] * RS2)) * RS2;
                float q1 = 0.5f * d[1] * (1.0f + erff(d[1] * RS2)) * RS2;
                float q2 = 0.5f * d[2] * (1.0f + erff(d[2] * RS2)) * RS2;
                float q3 = 0.5f * d[3] * (1.0f + erff(d[3] * RS2)) * RS2;
                *(float2*)&g_q[(size_t)r * FD + cc]       = make_float2(q0, q1);
                *(float2*)&g_q[(size_t)(r + 8) * FD + cc] = make_float2(q2, q3);
            } else if (wsel == 1) {
                float s0 = 1.0f / (1.0f + expf(-d[0]));
                float s1 = 1.0f / (1.0f + expf(-d[1]));
                float s2 = 1.0f / (1.0f + expf(-d[2]));
                float s3 = 1.0f / (1.0f + expf(-d[3]));
                *(float2*)&g_a[(size_t)r * FD + cc]       = make_float2(s0 + 1e-6f, s1 + 1e-6f);
                *(float2*)&g_a[(size_t)(r + 8) * FD + cc] = make_float2(s2 + 1e-6f, s3 + 1e-6f);
                *(float2*)&g_k[(size_t)r * FD + cc]       = make_float2(1.0f - s0, 1.0f - s1);
                *(float2*)&g_k[(size_t)(r + 8) * FD + cc] = make_float2(1.0f - s2, 1.0f - s3);
            } else {
                *(float2*)&g_v[(size_t)r * FD + cc]       = make_float2(d[0], d[1]);
                *(float2*)&g_v[(size_t)(r + 8) * FD + cc] = make_float2(d[2], d[3]);
            }
        }
    }
}

// ---------------- GEMM2: tanh_o @ Wo ----------------
// grid (8 n-tiles, 256 m-tiles); 256 threads; dyn smem 73728
__global__ void __launch_bounds__(256, 2) gemm2_kernel(float* __restrict__ out) {
    extern __shared__ char dsm[];
    uint32_t sb = smem_u32(dsm);

    int tid = threadIdx.x, wid = tid >> 5, lid = tid & 31;
    int g = lid >> 2, c = lid & 3;
    int wm = wid & 3, wn = wid >> 2;
    int n0 = blockIdx.x * 128;
    int m0 = blockIdx.y * 128;

    uint32_t aoff = a_lane_off(wm, lid);
    uint32_t boff = b_lane_off(wn, lid);

    float acc[2][8][4];
    #pragma unroll
    for (int mt = 0; mt < 2; mt++)
        #pragma unroll
        for (int nt = 0; nt < 8; nt++)
            #pragma unroll
            for (int j = 0; j < 4; j++) acc[mt][nt][j] = 0.f;

    for (int ch = 0; ch < 2; ch++) {
        int k0 = ch * 64;
        #pragma unroll
        for (int i = 0; i < 8; i++) {
            int u = tid + 256 * i;
            int row = u >> 4, f4 = u & 15;
            float4 v = *reinterpret_cast<const float4*>(g_to + (size_t)(m0 + row) * FD + k0 + f4 * 4);
            uint32_t h0, l0, h1, l1;
            split2(v.x, v.y, h0, l0); split2(v.z, v.w, h1, l1);
            uint32_t off = row * RSTR + f4 * 8;
            sts64(sb + A_H + off, h0, h1);
            sts64(sb + A_L + off, l0, l1);
        }
        #pragma unroll
        for (int i = 0; i < 8; i++) {
            int u = tid + 256 * i;
            int split = u >> 10, row = (u >> 3) & 127, seg = u & 7;
            uint4 d = *reinterpret_cast<const uint4*>(
                (split ? g_Wotl : g_Woth) + (size_t)(n0 + row) * FD + k0 + seg * 8);
            sts128(sb + (split ? B_L : B_H) + row * RSTR + seg * 16, d.x, d.y, d.z, d.w);
        }
        __syncthreads();
        gemm_compute64(sb, aoff, boff, acc);
        __syncthreads();
    }

    int row_base = m0 + wm * 32 + g;
    #pragma unroll
    for (int mt = 0; mt < 2; mt++) {
        #pragma unroll
        for (int nt = 0; nt < 8; nt++) {
            int r = row_base + mt * 16;
            int cc = n0 + wn * 64 + nt * 8 + 2 * c;
            float* d = acc[mt][nt];
            *(float2*)&out[(size_t)r * EDIM + cc]       = make_float2(d[0], d[1]);
            *(float2*)&out[(size_t)(r + 8) * EDIM + cc] = make_float2(d[2], d[3]);
        }
    }
}

// ---------------- scan pass A: per-chunk local scan ----------------
__global__ void __launch_bounds__(256) scanA_kernel() {
    int t = blockIdx.x;
    int b = threadIdx.x >> 6, h = threadIdx.x & 63;
    size_t base = ((size_t)b * LSEQ + (size_t)t * TCH) * FD + 2 * h;
    float S00 = 0.f, S01 = 0.f, S10 = 0.f, S11 = 0.f, A0 = 1.f, A1 = 1.f;
    #pragma unroll 4
    for (int i = 0; i < TCH; i++) {
        float2 a  = *(const float2*)&g_a[base];
        float2 kk = *(const float2*)&g_k[base];
        float2 vv = *(const float2*)&g_v[base];
        base += FD;
        S00 = a.x * S00 + kk.x * vv.x; S01 = a.x * S01 + kk.x * vv.y;
        S10 = a.y * S10 + kk.y * vv.x; S11 = a.y * S11 + kk.y * vv.y;
        A0 *= a.x; A1 *= a.y;
    }
    int ci = (b * NH + h) * NC + t;
    g_Ap0[ci] = A0;  g_Ap1[ci] = A1;
    g_L00[ci] = S00; g_L01[ci] = S01;
    g_L10[ci] = S10; g_L11[ci] = S11;
}

// ---------------- scan pass B: parallel Kogge-Stone combine over chunks --------
__global__ void __launch_bounds__(NC) scanB_kernel() {
    __shared__ float sA0[NC], sA1[NC];
    __shared__ float s00[NC], s01[NC], s10[NC], s11[NC];
    int bh = blockIdx.x;
    int t = threadIdx.x;
    size_t base = (size_t)bh * NC + t;

    float a0 = g_Ap0[base], a1 = g_Ap1[base];
    float l00 = g_L00[base], l01 = g_L01[base];
    float l10 = g_L10[base], l11 = g_L11[base];
    sA0[t] = a0; sA1[t] = a1;
    s00[t] = l00; s01[t] = l01; s10[t] = l10; s11[t] = l11;
    __syncthreads();

    #pragma unroll
    for (int d = 1; d < NC; d <<= 1) {
        float pa0 = 0.f, pa1 = 0.f, p00 = 0.f, p01 = 0.f, p10 = 0.f, p11 = 0.f;
        if (t >= d) {
            pa0 = sA0[t - d]; pa1 = sA1[t - d];
            p00 = s00[t - d]; p01 = s01[t - d];
            p10 = s10[t - d]; p11 = s11[t - d];
        }
        __syncthreads();
        if (t >= d) {
            l00 = fmaf(a0, p00, l00); l01 = fmaf(a0, p01, l01);
            l10 = fmaf(a1, p10, l10); l11 = fmaf(a1, p11, l11);
            a0 *= pa0; a1 *= pa1;
            sA0[t] = a0; sA1[t] = a1;
            s00[t] = l00; s01[t] = l01; s10[t] = l10; s11[t] = l11;
        }
        __syncthreads();
    }

    float i00 = 0.f, i01 = 0.f, i10 = 0.f, i11 = 0.f;
    if (t > 0) {
        i00 = s00[t - 1]; i01 = s01[t - 1];
        i10 = s10[t - 1]; i11 = s11[t - 1];
    }
    g_I00[base] = i00; g_I01[base] = i01;
    g_I10[base] = i10; g_I11[base] = i11;
}

// ---------------- scan pass C: replay + tanh ----------------
__global__ void __launch_bounds__(256) scanC_kernel() {
    int t = blockIdx.x;
    int b = threadIdx.x >> 6, h = threadIdx.x & 63;
    int ci = (b * NH + h) * NC + t;
    float S00 = g_I00[ci], S01 = g_I01[ci], S10 = g_I10[ci], S11 = g_I11[ci];
    size_t base = ((size_t)b * LSEQ + (size_t)t * TCH) * FD + 2 * h;
    #pragma unroll 4
    for (int i = 0; i < TCH; i++) {
        float2 a  = *(const float2*)&g_a[base];
        float2 kk = *(const float2*)&g_k[base];
        float2 vv = *(const float2*)&g_v[base];
        float2 q  = *(const float2*)&g_q[base];
        S00 = a.x * S00 + kk.x * vv.x; S01 = a.x * S01 + kk.x * vv.y;
        S10 = a.y * S10 + kk.y * vv.x; S11 = a.y * S11 + kk.y * vv.y;
        float ox = q.x * S00 + q.y * S10;
        float oy = q.x * S01 + q.y * S11;
        *(float2*)&g_to[base] = make_float2(tanhf(ox), tanhf(oy));
        base += FD;
    }
}

// ---------------- launch ----------------
extern "C" void kernel_launch(void* const* d_in, const int* in_sizes, int n_in,
                              void* d_out, int out_size) {
    const float* x  = (const float*)d_in[0];
    const float* Wq = (const float*)d_in[1];
    const float* Wf = (const float*)d_in[2];
    const float* Wi = (const float*)d_in[3];
    const float* Wo = (const float*)d_in[4];
    float* out = (float*)d_out;

    static int configured = 0;
    if (!configured) {
        cudaFuncSetAttribute(gemm1_kernel, cudaFuncAttributeMaxDynamicSharedMemorySize, SMEM_BYTES);
        cudaFuncSetAttribute(gemm2_kernel, cudaFuncAttributeMaxDynamicSharedMemorySize, SMEM_BYTES);
        configured = 1;
    }

    prep_w_kernel<<<2048, 256>>>(Wq, Wf, Wi, Wo);
    gemm1_kernel<<<dim3(3, MTOT / 128), 256, SMEM_BYTES>>>(x);
    scanA_kernel<<<NC, 256>>>();
    scanB_kernel<<<NBH, NC>>>();
    scanC_kernel<<<NC, 256>>>();
    gemm2_kernel<<<dim3(8, MTOT / 128), 256, SMEM_BYTES>>>(out);
}